// round 4
// baseline (speedup 1.0000x reference)
#include <cuda_runtime.h>

typedef unsigned long long u64;

#define BB 2048
#define TT 4096
#define II 5
#define HH 10

// ---- packed fp32x2 helpers ----
__device__ __forceinline__ u64 pk2(float lo, float hi) {
    u64 r; asm("mov.b64 %0, {%1,%2};" : "=l"(r) : "f"(lo), "f"(hi)); return r;
}
__device__ __forceinline__ void upk2(u64 v, float &lo, float &hi) {
    asm("mov.b64 {%0,%1}, %2;" : "=f"(lo), "=f"(hi) : "l"(v));
}
__device__ __forceinline__ u64 fma2(u64 a, u64 b, u64 c) {
    u64 d; asm("fma.rn.f32x2 %0, %1, %2, %3;" : "=l"(d) : "l"(a), "l"(b), "l"(c)); return d;
}
__device__ __forceinline__ u64 mul2(u64 a, u64 b) {
    u64 d; asm("mul.rn.f32x2 %0, %1, %2;" : "=l"(d) : "l"(a), "l"(b)); return d;
}
// ---- MUFU ops ----
__device__ __forceinline__ float ex2f(float x) { float r; asm("ex2.approx.ftz.f32 %0, %1;" : "=f"(r) : "f"(x)); return r; }
__device__ __forceinline__ float rcpf(float x) { float r; asm("rcp.approx.ftz.f32 %0, %1;" : "=f"(r) : "f"(x)); return r; }
__device__ __forceinline__ float tanhf_(float x) { float r; asm("tanh.approx.f32 %0, %1;" : "=f"(r) : "f"(x)); return r; }

#define S_TANH (-2.8853900817779268f)  // -2*log2(e): exact tanh(c) prescale

// Layout: 16 lanes per batch element (unit j on lanes 0..9 of each half-warp,
// lanes 10..15 idle), 2 elements per warp -> 1024 warps (1.73/SMSP) so that
// independent recurrence chains in different warps overlap on each scheduler.
// Gate activations use single-MUFU tanh.approx (sigmoid = 0.5+0.5*tanh(x/2),
// the 0.5 prescale folded into weights); tanh(c) stays on the exact ex2/rcp
// path to protect rel_err.
__global__ void __launch_bounds__(128, 1) lstm_kernel(
    const float* __restrict__ x,   const float* __restrict__ h0,
    const float* __restrict__ c0,  const float* __restrict__ Wih,
    const float* __restrict__ Whh, const float* __restrict__ bih,
    const float* __restrict__ bhh, float* __restrict__ out)
{
    const int lane  = threadIdx.x & 31;
    const int gwarp = (blockIdx.x * blockDim.x + threadIdx.x) >> 5;   // 0..1023

    const int grp   = lane >> 4;            // element within warp: 0 or 1
    const int j     = lane & 15;            // unit index; >=10 -> idle lane
    const bool valid = (j < HH);
    const int jj    = valid ? j : 0;        // clamped for safe loads
    const int b     = gwarp * 2 + grp;      // < 2048 always (1024 warps * 2)
    const int base  = grp << 4;             // shfl source base lane

    // ---- pre-scaled per-thread weights ----
    // gates i,f,o: scale 0.5 (tanh half-argument form); gate g: scale 1.
    u64 wh[4][5];
    u64 wx01[4], wx23[4];
    float wx4[4], bs[4];
#pragma unroll
    for (int g = 0; g < 4; g++) {
        const float s = (g == 2) ? 1.0f : 0.5f;
        const int row = (g * HH + jj);
#pragma unroll
        for (int m = 0; m < 5; m++)
            wh[g][m] = pk2(s * Whh[row * HH + 2 * m], s * Whh[row * HH + 2 * m + 1]);
        wx01[g] = pk2(s * Wih[row * II + 0], s * Wih[row * II + 1]);
        wx23[g] = pk2(s * Wih[row * II + 2], s * Wih[row * II + 3]);
        wx4[g]  = s * Wih[row * II + 4];
        bs[g]   = s * (bih[g * HH + jj] + bhh[g * HH + jj]);
    }

    float h = h0[b * HH + jj];
    float c = c0[b * HH + jj];

    const float* xp = x   + (size_t)b * TT * II;
    float*       op = out + (size_t)b * TT * HH + jj;

    // x double buffers: 4 timesteps (20 floats) each, as 5 x float4.
    // (b*T + t)*I*4B is 16B-aligned whenever t%4==0.
    float xa[20], xb[20];
#pragma unroll
    for (int q = 0; q < 5; q++) {
        float4 v = *reinterpret_cast<const float4*>(xp + 4 * q);
        xa[4 * q + 0] = v.x; xa[4 * q + 1] = v.y;
        xa[4 * q + 2] = v.z; xa[4 * q + 3] = v.w;
    }

    auto STEP = [&](const float* xs, int t) {
        // x-part (independent of h; scheduler hoists above the shfl wait)
        u64 x01 = pk2(xs[0], xs[1]);
        u64 x23 = pk2(xs[2], xs[3]);
        const float x4 = xs[4];

        u64 acc[4];
        float tg[4];
#pragma unroll
        for (int g = 0; g < 4; g++) {
            acc[g] = fma2(wx01[g], x01, mul2(wx23[g], x23));
            tg[g]  = fmaf(wx4[g], x4, bs[g]);
        }

        // h-part: pair (h_2m, h_2m+1) from two shfls -> direct fma2 operand
#pragma unroll
        for (int m = 0; m < 5; m++) {
            float lo = __shfl_sync(0xffffffffu, h, base + 2 * m);
            float hi = __shfl_sync(0xffffffffu, h, base + 2 * m + 1);
            u64 hp = pk2(lo, hi);
#pragma unroll
            for (int g = 0; g < 4; g++)
                acc[g] = fma2(wh[g][m], hp, acc[g]);
        }

        // combine halves + activations
        float pre[4];
#pragma unroll
        for (int g = 0; g < 4; g++) {
            float lo, hi; upk2(acc[g], lo, hi);
            pre[g] = (lo + hi) + tg[g];
        }
        // sigmoid(x) = 0.5 + 0.5*tanh(x/2); x/2 already in pre via prescale
        float si = fmaf(0.5f, tanhf_(pre[0]), 0.5f);
        float sf = fmaf(0.5f, tanhf_(pre[1]), 0.5f);
        float gg = tanhf_(pre[2]);
        float so = fmaf(0.5f, tanhf_(pre[3]), 0.5f);
        c = fmaf(sf, c, si * gg);
        // exact tanh(c) = 2/(1+2^(S_TANH*c)) - 1  (feeds the output directly)
        float tc = fmaf(2.0f, rcpf(1.0f + ex2f(S_TANH * c)), -1.0f);
        h = so * tc;
        if (valid) op[(size_t)t * HH] = h;
    };

    for (int tb = 0; tb < TT; tb += 8) {
        // prefetch next 4 steps into xb while computing from xa
#pragma unroll
        for (int q = 0; q < 5; q++) {
            float4 v = *reinterpret_cast<const float4*>(xp + (tb + 4) * II + 4 * q);
            xb[4 * q + 0] = v.x; xb[4 * q + 1] = v.y;
            xb[4 * q + 2] = v.z; xb[4 * q + 3] = v.w;
        }
#pragma unroll
        for (int s = 0; s < 4; s++)
            STEP(&xa[s * 5], tb + s);

        if (tb + 8 < TT) {
#pragma unroll
            for (int q = 0; q < 5; q++) {
                float4 v = *reinterpret_cast<const float4*>(xp + (tb + 8) * II + 4 * q);
                xa[4 * q + 0] = v.x; xa[4 * q + 1] = v.y;
                xa[4 * q + 2] = v.z; xa[4 * q + 3] = v.w;
            }
        }
#pragma unroll
        for (int s = 0; s < 4; s++)
            STEP(&xb[s * 5], tb + 4 + s);
    }
}

extern "C" void kernel_launch(void* const* d_in, const int* in_sizes, int n_in,
                              void* d_out, int out_size)
{
    const float* x   = (const float*)d_in[0];
    const float* h0  = (const float*)d_in[1];
    const float* c0  = (const float*)d_in[2];
    const float* Wih = (const float*)d_in[3];
    const float* Whh = (const float*)d_in[4];
    const float* bih = (const float*)d_in[5];
    const float* bhh = (const float*)d_in[6];
    float* out = (float*)d_out;

    // 1024 warps total: 2 elements per warp, 16 lanes per element.
    const int threads = 128;
    const int blocks  = (BB / 2) * 32 / threads;   // 256
    lstm_kernel<<<blocks, threads>>>(x, h0, c0, Wih, Whh, bih, bhh, out);
}

// round 5
// speedup vs baseline: 1.1656x; 1.1656x over previous
#include <cuda_runtime.h>

typedef unsigned long long u64;

#define BB 2048
#define TT 4096
#define II 5
#define HH 10

// ---- packed fp32x2 helpers ----
__device__ __forceinline__ u64 pk2(float lo, float hi) {
    u64 r; asm("mov.b64 %0, {%1,%2};" : "=l"(r) : "f"(lo), "f"(hi)); return r;
}
__device__ __forceinline__ void upk2(u64 v, float &lo, float &hi) {
    asm("mov.b64 {%0,%1}, %2;" : "=f"(lo), "=f"(hi) : "l"(v));
}
__device__ __forceinline__ u64 fma2(u64 a, u64 b, u64 c) {
    u64 d; asm("fma.rn.f32x2 %0, %1, %2, %3;" : "=l"(d) : "l"(a), "l"(b), "l"(c)); return d;
}
// ---- single-MUFU tanh (R3 measured: gate-side use gave rel_err 4.7e-6) ----
__device__ __forceinline__ float tanhf_(float x) { float r; asm("tanh.approx.f32 %0, %1;" : "=f"(r) : "f"(x)); return r; }

// Layout: 16 lanes per batch element (unit j on lanes 0..9 of each half-warp),
// 2 elements per warp -> 1024 warps. The kernel is bound by the per-timestep
// serial chain L (R1-R3: dur invariant at ~845us across occupancy/instruction
// changes). This version minimizes L:
//   - all 10 h-shfls issued first, latency overlapped with the x-part
//   - x+bias folded into the f32x2 accumulator init (combine = one FADD)
//   - tanh.approx on ALL activations including tanh(c) (16 cyc vs 44)
__global__ void __launch_bounds__(128, 1) lstm_kernel(
    const float* __restrict__ x,   const float* __restrict__ h0,
    const float* __restrict__ c0,  const float* __restrict__ Wih,
    const float* __restrict__ Whh, const float* __restrict__ bih,
    const float* __restrict__ bhh, float* __restrict__ out)
{
    const int lane  = threadIdx.x & 31;
    const int gwarp = (blockIdx.x * blockDim.x + threadIdx.x) >> 5;   // 0..1023

    const int grp   = lane >> 4;            // element within warp: 0 or 1
    const int j     = lane & 15;            // unit index; >=10 -> idle lane
    const bool valid = (j < HH);
    const int jj    = valid ? j : 0;        // clamped for safe loads
    const int b     = gwarp * 2 + grp;      // < 2048 always
    const int base  = grp << 4;             // shfl source base lane

    // ---- pre-scaled per-thread weights ----
    // gates i,f,o: x0.5 (sigmoid(x) = 0.5 + 0.5*tanh(x/2)); gate g: x1.
    u64 wh[4][5];                  // h k-pairs (2m, 2m+1)
    u64 wx01[4], wx23[4];
    float wx4[4], bs[4];
#pragma unroll
    for (int g = 0; g < 4; g++) {
        const float s = (g == 2) ? 1.0f : 0.5f;
        const int row = (g * HH + jj);
#pragma unroll
        for (int m = 0; m < 5; m++)
            wh[g][m] = pk2(s * Whh[row * HH + 2 * m], s * Whh[row * HH + 2 * m + 1]);
        wx01[g] = pk2(s * Wih[row * II + 0], s * Wih[row * II + 1]);
        wx23[g] = pk2(s * Wih[row * II + 2], s * Wih[row * II + 3]);
        wx4[g]  = s * Wih[row * II + 4];
        bs[g]   = s * (bih[g * HH + jj] + bhh[g * HH + jj]);
    }

    float h = h0[b * HH + jj];
    float c = c0[b * HH + jj];

    const float* xp = x   + (size_t)b * TT * II;
    float*       op = out + (size_t)b * TT * HH + jj;

    // x double buffers: 4 timesteps (20 floats) each, as 5 x float4.
    // (b*T + t)*I*4B is 16B-aligned whenever t%4==0.
    float xa[20], xb[20];
#pragma unroll
    for (int q = 0; q < 5; q++) {
        float4 v = *reinterpret_cast<const float4*>(xp + 4 * q);
        xa[4 * q + 0] = v.x; xa[4 * q + 1] = v.y;
        xa[4 * q + 2] = v.z; xa[4 * q + 3] = v.w;
    }

    auto STEP = [&](const float* xs, int t) {
        // 1) launch all h broadcasts immediately (longest-latency producers)
        float hs[10];
#pragma unroll
        for (int k = 0; k < 10; k++)
            hs[k] = __shfl_sync(0xffffffffu, h, base + k);

        // 2) x-part + bias, independent of h: becomes the chain base so the
        //    final combine is a single lo+hi FADD.
        u64 x01 = pk2(xs[0], xs[1]);
        u64 x23 = pk2(xs[2], xs[3]);
        const float x4 = xs[4];

        u64 acc[4];
#pragma unroll
        for (int g = 0; g < 4; g++) {
            float tg = fmaf(wx4[g], x4, bs[g]);
            acc[g] = fma2(wx23[g], x23, pk2(tg, 0.0f));
            acc[g] = fma2(wx01[g], x01, acc[g]);
        }

        // 3) h-dot: pair (h_2m, h_2m+1) -> fma2; later-landing shfls feed
        //    later links of the chain.
#pragma unroll
        for (int m = 0; m < 5; m++) {
            u64 hp = pk2(hs[2 * m], hs[2 * m + 1]);
#pragma unroll
            for (int g = 0; g < 4; g++)
                acc[g] = fma2(wh[g][m], hp, acc[g]);
        }

        // 4) combine + activations (all single-MUFU tanh.approx)
        float pre[4];
#pragma unroll
        for (int g = 0; g < 4; g++) {
            float lo, hi; upk2(acc[g], lo, hi);
            pre[g] = lo + hi;
        }
        float si = fmaf(0.5f, tanhf_(pre[0]), 0.5f);
        float sf = fmaf(0.5f, tanhf_(pre[1]), 0.5f);
        float gg = tanhf_(pre[2]);
        float so = fmaf(0.5f, tanhf_(pre[3]), 0.5f);
        c = fmaf(sf, c, si * gg);
        h = so * tanhf_(c);
        if (valid) op[(size_t)t * HH] = h;
    };

    for (int tb = 0; tb < TT; tb += 8) {
        // prefetch next 4 steps into xb while computing from xa
#pragma unroll
        for (int q = 0; q < 5; q++) {
            float4 v = *reinterpret_cast<const float4*>(xp + (tb + 4) * II + 4 * q);
            xb[4 * q + 0] = v.x; xb[4 * q + 1] = v.y;
            xb[4 * q + 2] = v.z; xb[4 * q + 3] = v.w;
        }
#pragma unroll
        for (int s = 0; s < 4; s++)
            STEP(&xa[s * 5], tb + s);

        if (tb + 8 < TT) {
#pragma unroll
            for (int q = 0; q < 5; q++) {
                float4 v = *reinterpret_cast<const float4*>(xp + (tb + 8) * II + 4 * q);
                xa[4 * q + 0] = v.x; xa[4 * q + 1] = v.y;
                xa[4 * q + 2] = v.z; xa[4 * q + 3] = v.w;
            }
        }
#pragma unroll
        for (int s = 0; s < 4; s++)
            STEP(&xb[s * 5], tb + 4 + s);
    }
}

extern "C" void kernel_launch(void* const* d_in, const int* in_sizes, int n_in,
                              void* d_out, int out_size)
{
    const float* x   = (const float*)d_in[0];
    const float* h0  = (const float*)d_in[1];
    const float* c0  = (const float*)d_in[2];
    const float* Wih = (const float*)d_in[3];
    const float* Whh = (const float*)d_in[4];
    const float* bih = (const float*)d_in[5];
    const float* bhh = (const float*)d_in[6];
    float* out = (float*)d_out;

    // 1024 warps: 2 elements per warp, 16 lanes per element.
    const int threads = 128;
    const int blocks  = (BB / 2) * 32 / threads;   // 256
    lstm_kernel<<<blocks, threads>>>(x, h0, c0, Wih, Whh, bih, bhh, out);
}

// round 6
// speedup vs baseline: 1.2181x; 1.0451x over previous
#include <cuda_runtime.h>

typedef unsigned long long u64;

#define BB 2048
#define TT 4096
#define II 5
#define HH 10

// ---- packed fp32x2 helpers ----
__device__ __forceinline__ u64 pk2(float lo, float hi) {
    u64 r; asm("mov.b64 %0, {%1,%2};" : "=l"(r) : "f"(lo), "f"(hi)); return r;
}
__device__ __forceinline__ void upk2(u64 v, float &lo, float &hi) {
    asm("mov.b64 {%0,%1}, %2;" : "=f"(lo), "=f"(hi) : "l"(v));
}
__device__ __forceinline__ u64 fma2(u64 a, u64 b, u64 c) {
    u64 d; asm("fma.rn.f32x2 %0, %1, %2, %3;" : "=l"(d) : "l"(a), "l"(b), "l"(c)); return d;
}
__device__ __forceinline__ u64 add2(u64 a, u64 b) {
    u64 d; asm("add.rn.f32x2 %0, %1, %2;" : "=l"(d) : "l"(a), "l"(b)); return d;
}
__device__ __forceinline__ float tanhf_(float x) { float r; asm("tanh.approx.f32 %0, %1;" : "=f"(r) : "f"(x)); return r; }

// h broadcast via shared memory instead of 10 SHFLs:
//   writer: 1 x st.volatile.shared.f32 (own h)
//   reader: 2 x ld.volatile.shared.v4 + 1 x ld.volatile.shared.v2
// Same warp issues STS before LDS; smem pipeline is in-order per warp and
// sm_103a has no store-forwarding (stores commit directly), so no syncwarp.
// v4/v2 loads land as register pairs -> direct fma2 operands (no pk2 MOVs).
__global__ void __launch_bounds__(128, 1) lstm_kernel(
    const float* __restrict__ x,   const float* __restrict__ h0,
    const float* __restrict__ c0,  const float* __restrict__ Wih,
    const float* __restrict__ Whh, const float* __restrict__ bih,
    const float* __restrict__ bhh, float* __restrict__ out)
{
    // per-CTA smem: 8 elements x 16 floats (64B stride keeps the two elements
    // of a warp on disjoint banks; slots 10..15 are idle-lane scratch)
    __shared__ float hbuf[8][16];

    const int lane  = threadIdx.x & 31;
    const int gwarp = (blockIdx.x * blockDim.x + threadIdx.x) >> 5;   // 0..1023

    const int grp   = lane >> 4;            // element within warp: 0 or 1
    const int j     = lane & 15;            // unit index; >=10 -> idle lane
    const bool valid = (j < HH);
    const int jj    = valid ? j : 0;        // clamped for weight loads
    const int b     = gwarp * 2 + grp;      // < 2048 always
    const int elem  = ((threadIdx.x >> 5) << 1) + grp;   // 0..7 within CTA

    // smem addresses (32-bit shared window)
    unsigned hb_store, hb_base;
    {
        unsigned base;
        asm("{ .reg .u64 t; cvta.to.shared.u64 t, %1; cvt.u32.u64 %0, t; }"
            : "=r"(base) : "l"(&hbuf[elem][0]));
        hb_base  = base;
        hb_store = base + (unsigned)(j * 4);   // idle lanes -> scratch slots
    }

    // ---- pre-scaled per-thread weights ----
    // gates i,f,o: x0.5 (sigmoid(x) = 0.5 + 0.5*tanh(x/2)); gate g: x1.
    u64 wh[4][5];
    u64 wx01[4], wx23[4];
    float wx4[4], bs[4];
#pragma unroll
    for (int g = 0; g < 4; g++) {
        const float s = (g == 2) ? 1.0f : 0.5f;
        const int row = (g * HH + jj);
#pragma unroll
        for (int m = 0; m < 5; m++)
            wh[g][m] = pk2(s * Whh[row * HH + 2 * m], s * Whh[row * HH + 2 * m + 1]);
        wx01[g] = pk2(s * Wih[row * II + 0], s * Wih[row * II + 1]);
        wx23[g] = pk2(s * Wih[row * II + 2], s * Wih[row * II + 3]);
        wx4[g]  = s * Wih[row * II + 4];
        bs[g]   = s * (bih[g * HH + jj] + bhh[g * HH + jj]);
    }

    float h = h0[b * HH + jj];
    float c = c0[b * HH + jj];

    const float* xp = x   + (size_t)b * TT * II;
    float*       op = out + (size_t)b * TT * HH + jj;

    // seed the h buffer with h0
    asm volatile("st.volatile.shared.f32 [%0], %1;" :: "r"(hb_store), "f"(h));

    // x double buffers: 4 timesteps (20 floats) each, as 5 x float4.
    float xa[20], xb[20];
#pragma unroll
    for (int q = 0; q < 5; q++) {
        float4 v = *reinterpret_cast<const float4*>(xp + 4 * q);
        xa[4 * q + 0] = v.x; xa[4 * q + 1] = v.y;
        xa[4 * q + 2] = v.z; xa[4 * q + 3] = v.w;
    }

    auto STEP = [&](const float* xs, int t) {
        // 1) gather all 10 h values: 3 vector LDS (pairs land fma2-ready)
        float h0_, h1_, h2_, h3_, h4_, h5_, h6_, h7_, h8_, h9_;
        asm volatile("ld.volatile.shared.v4.f32 {%0,%1,%2,%3}, [%4];"
                     : "=f"(h0_), "=f"(h1_), "=f"(h2_), "=f"(h3_) : "r"(hb_base));
        asm volatile("ld.volatile.shared.v4.f32 {%0,%1,%2,%3}, [%4+16];"
                     : "=f"(h4_), "=f"(h5_), "=f"(h6_), "=f"(h7_) : "r"(hb_base));
        asm volatile("ld.volatile.shared.v2.f32 {%0,%1}, [%2+32];"
                     : "=f"(h8_), "=f"(h9_) : "r"(hb_base));
        u64 hp0 = pk2(h0_, h1_), hp1 = pk2(h2_, h3_), hp2 = pk2(h4_, h5_),
            hp3 = pk2(h6_, h7_), hp4 = pk2(h8_, h9_);

        // 2) x-part + bias (independent of h)
        u64 x01 = pk2(xs[0], xs[1]);
        u64 x23 = pk2(xs[2], xs[3]);
        const float x4 = xs[4];

        // 3) two parallel fma2 chains per gate, then add2
        float pre[4];
#pragma unroll
        for (int g = 0; g < 4; g++) {
            float tg = fmaf(wx4[g], x4, bs[g]);
            u64 a = fma2(wx23[g], x23, pk2(tg, 0.0f));
            u64 d = fma2(wx01[g], x01, pk2(0.0f, 0.0f));
            a = fma2(wh[g][0], hp0, a);
            d = fma2(wh[g][1], hp1, d);
            a = fma2(wh[g][2], hp2, a);
            d = fma2(wh[g][3], hp3, d);
            a = fma2(wh[g][4], hp4, a);
            u64 s2 = add2(a, d);
            float lo, hi; upk2(s2, lo, hi);
            pre[g] = lo + hi;
        }

        // 4) activations: c-path gates first, o-gate next, tanh(c) last
        float si = fmaf(0.5f, tanhf_(pre[0]), 0.5f);
        float sf = fmaf(0.5f, tanhf_(pre[1]), 0.5f);
        float gg = tanhf_(pre[2]);
        float so = fmaf(0.5f, tanhf_(pre[3]), 0.5f);
        c = fmaf(sf, c, si * gg);
        h = so * tanhf_(c);

        // 5) publish h for next step + output
        asm volatile("st.volatile.shared.f32 [%0], %1;" :: "r"(hb_store), "f"(h));
        if (valid) op[(size_t)t * HH] = h;
    };

    for (int tb = 0; tb < TT; tb += 8) {
#pragma unroll
        for (int q = 0; q < 5; q++) {
            float4 v = *reinterpret_cast<const float4*>(xp + (tb + 4) * II + 4 * q);
            xb[4 * q + 0] = v.x; xb[4 * q + 1] = v.y;
            xb[4 * q + 2] = v.z; xb[4 * q + 3] = v.w;
        }
#pragma unroll
        for (int s = 0; s < 4; s++)
            STEP(&xa[s * 5], tb + s);

        if (tb + 8 < TT) {
#pragma unroll
            for (int q = 0; q < 5; q++) {
                float4 v = *reinterpret_cast<const float4*>(xp + (tb + 8) * II + 4 * q);
                xa[4 * q + 0] = v.x; xa[4 * q + 1] = v.y;
                xa[4 * q + 2] = v.z; xa[4 * q + 3] = v.w;
            }
        }
#pragma unroll
        for (int s = 0; s < 4; s++)
            STEP(&xb[s * 5], tb + 4 + s);
    }
}

extern "C" void kernel_launch(void* const* d_in, const int* in_sizes, int n_in,
                              void* d_out, int out_size)
{
    const float* x   = (const float*)d_in[0];
    const float* h0  = (const float*)d_in[1];
    const float* c0  = (const float*)d_in[2];
    const float* Wih = (const float*)d_in[3];
    const float* Whh = (const float*)d_in[4];
    const float* bih = (const float*)d_in[5];
    const float* bhh = (const float*)d_in[6];
    float* out = (float*)d_out;

    // 1024 warps: 2 elements per warp, 16 lanes per element.
    const int threads = 128;
    const int blocks  = (BB / 2) * 32 / threads;   // 256
    lstm_kernel<<<blocks, threads>>>(x, h0, c0, Wih, Whh, bih, bhh, out);
}